// round 15
// baseline (speedup 1.0000x reference)
#include <cuda_runtime.h>
#include <cuda_fp16.h>
#include <math.h>
#include <stdint.h>
#include <stddef.h>

#define BB 64
#define SS 2048
#define HH 1024
#define NEGV -1e10f

// ---------------- tiling (R12 winner: KSTG=128, 2-deep ring) ----------------
#define KSTG 128                    // K elems per pipeline stage (8 x k16)
#define NTILE 256                   // N per pass
#define NPASS 4
#define SPP (HH / KSTG)             // 8 stages per pass
#define TOTS (NPASS * SPP)          // 32 stages
#define ASTRH 136                   // A smem row stride in halves (272 B = 17x16B, LDSM bank-clean)
#define BSTRW 264                   // B smem row stride in words (LDS.128 bank-clean)
#define ASTG (128 * ASTRH * 2)      // 34816 B
#define BSTG (64 * BSTRW * 4)       // 67584 B
#define SC_OFF 0
#define SV_OFF 4096
#define SRED_OFF 8192
#define A_OFF 10240
#define B_OFF (A_OFF + 2 * ASTG)              // 79872
#define SMEM_TOTAL (B_OFF + 2 * BSTG)         // 215040 bytes

__device__ float g_c[BB * HH];
__device__ float g_cpart[8 * BB * HH];
__device__ float g_logits[BB * SS];
__device__ __half g_encH[(size_t)BB * SS * HH];   // enc in fp16
__device__ uint32_t g_WeH[(HH / 2) * HH];         // We fp16x2 (k-pairs), col-permuted

// ---------------- helpers ----------------
static __device__ __forceinline__ float tanh_fast(float x) {
    float y;
    asm("tanh.approx.f32 %0, %1;" : "=f"(y) : "f"(x));
    return y;
}
static __device__ __forceinline__ uint32_t smem_u32(const void* p) {
    uint32_t a;
    asm("{ .reg .u64 t; cvta.to.shared.u64 t, %1; cvt.u32.u64 %0, t; }" : "=r"(a) : "l"(p));
    return a;
}
static __device__ __forceinline__ void cp16(uint32_t d, const void* s) {
    asm volatile("cp.async.cg.shared.global [%0], [%1], 16;" :: "r"(d), "l"(s) : "memory");
}
#define CP_COMMIT() asm volatile("cp.async.commit_group;" ::: "memory")

// ---------------------------------------------------------------------------
// Prep 1a: enc -> fp16
// ---------------------------------------------------------------------------
__global__ void conv_enc(const float* __restrict__ enc) {
    size_t idx = ((size_t)blockIdx.x * 256 + threadIdx.x) * 8;
    const float4 f0 = *(const float4*)(enc + idx);
    const float4 f1 = *(const float4*)(enc + idx + 4);
    __half2 h0 = __floats2half2_rn(f0.x, f0.y);
    __half2 h1 = __floats2half2_rn(f0.z, f0.w);
    __half2 h2 = __floats2half2_rn(f1.x, f1.y);
    __half2 h3 = __floats2half2_rn(f1.z, f1.w);
    uint4 o;
    o.x = *(uint32_t*)&h0; o.y = *(uint32_t*)&h1;
    o.z = *(uint32_t*)&h2; o.w = *(uint32_t*)&h3;
    *(uint4*)(g_encH + idx) = o;
}

// ---------------------------------------------------------------------------
// Prep 1b: We -> fp16x2 k-pair packed, col-permuted within 32-col groups
// ---------------------------------------------------------------------------
__global__ void conv_we(const float* __restrict__ Wa) {
    const float* We = Wa + (size_t)HH * HH;
    const int kp = blockIdx.y;
    const int n = blockIdx.x * 256 + threadIdx.x;
    float a = We[(size_t)(2 * kp) * HH + n];
    float b = We[(size_t)(2 * kp + 1) * HH + n];
    __half2 h = __floats2half2_rn(a, b);
    int r = n & 31;
    int cc = (n & ~31) + (r & 7) * 4 + (r >> 3);
    g_WeH[(size_t)kp * HH + cc] = *(uint32_t*)&h;
}

// ---------------------------------------------------------------------------
// Prep 2: dec_proj k-split partials, batch-split 4x (deterministic)
// ---------------------------------------------------------------------------
__global__ void __launch_bounds__(128) decproj_part(const float* __restrict__ dh,
                                                    const float* __restrict__ Wa) {
    __shared__ float sdh[16 * 128];
    const int tid = threadIdx.x;
    const int h = blockIdx.x * 128 + tid;
    const int k0 = blockIdx.y * 128;
    const int b0 = blockIdx.z * 16;
    for (int i = tid; i < 16 * 128; i += 128) {
        int b = i >> 7, kk = i & 127;
        sdh[i] = dh[(b0 + b) * HH + k0 + kk];
    }
    __syncthreads();
    float acc[16];
#pragma unroll
    for (int b = 0; b < 16; b++) acc[b] = 0.f;
    for (int kk = 0; kk < 128; kk++) {
        float w = Wa[(size_t)(k0 + kk) * HH + h];
#pragma unroll
        for (int b = 0; b < 16; b++) acc[b] += sdh[b * 128 + kk] * w;
    }
#pragma unroll
    for (int b = 0; b < 16; b++)
        g_cpart[((size_t)blockIdx.y * BB + b0 + b) * HH + h] = acc[b];
}

__global__ void decproj_reduce(const float* __restrict__ ba) {
    int b = blockIdx.x;
    for (int h = threadIdx.x; h < HH; h += 256) {
        float s = ba[h];
#pragma unroll
        for (int kc = 0; kc < 8; kc++) s += g_cpart[((size_t)kc * BB + b) * HH + h];
        g_c[b * HH + h] = s;
    }
}

// ---------------------------------------------------------------------------
// Fragment load macro (one ks group): 4x LDSM.x4 for A, 4x LDS.128 for B
// ---------------------------------------------------------------------------
#define LOAD_FRAGS(ksv) do { \
        _Pragma("unroll") \
        for (int mi = 0; mi < 4; mi++) \
            asm volatile( \
                "ldmatrix.sync.aligned.m8n8.x4.shared.b16 {%0,%1,%2,%3}, [%4];" \
                : "=r"(afr[mi][0]), "=r"(afr[mi][1]), \
                  "=r"(afr[mi][2]), "=r"(afr[mi][3]) \
                : "r"(aLd + mi * 16 * (ASTRH * 2) + (ksv) * 32)); \
        const char* bk = bGen + (ksv) * 8 * (BSTRW * 4); \
        const uint4 x0g0 = *(const uint4*)(bk); \
        const uint4 x0g1 = *(const uint4*)(bk + 128); \
        const uint4 x1g0 = *(const uint4*)(bk + 4 * (BSTRW * 4)); \
        const uint4 x1g1 = *(const uint4*)(bk + 4 * (BSTRW * 4) + 128); \
        b0[0] = x0g0.x; b0[1] = x0g0.y; b0[2] = x0g0.z; b0[3] = x0g0.w; \
        b0[4] = x0g1.x; b0[5] = x0g1.y; b0[6] = x0g1.z; b0[7] = x0g1.w; \
        b1[0] = x1g0.x; b1[1] = x1g0.y; b1[2] = x1g0.z; b1[3] = x1g0.w; \
        b1[4] = x1g1.x; b1[5] = x1g1.y; b1[6] = x1g1.z; b1[7] = x1g1.w; \
    } while (0)

// ---------------------------------------------------------------------------
// Fused main: fp16 m16n8k16, 256 threads (2wm x 4wn, M64 x N64 warp tile),
// KSTG=128 (8 x k16), 2-deep cp.async ring. Peeled ks pipeline: frags(ks0)
// load precedes the fill burst; frags(ks+1) issue under MMA(ks) drain.
// ---------------------------------------------------------------------------
__global__ void __launch_bounds__(256, 1) attn_kernel(const int* __restrict__ mask,
                                                      const float* __restrict__ vw) {
    extern __shared__ char smem[];
    float* sC = (float*)(smem + SC_OFF);
    float* sV = (float*)(smem + SV_OFF);
    float* sRed = (float*)(smem + SRED_OFF);

    const int tid = threadIdx.x;
    const int wid = tid >> 5, lane = tid & 31;
    const int wm = wid & 1;        // 2 warps along M (64 rows each)
    const int wn = wid >> 1;       // 4 warps along N (64 cols each)
    const int g = lane >> 2, t = lane & 3;
    const int cta = blockIdx.x;
    const int bb = cta >> 4;
    const int m0 = (cta & 15) * 128;
    const __half* encHb = g_encH + ((size_t)bb * SS + m0) * HH;

    // ldmatrix b16 x4 lane offsets
    const int ltile = lane >> 3, lrow = lane & 7;
    const int lm_row = (ltile & 1) * 8 + lrow;
    const int lm_colB = (ltile >> 1) * 16;

    for (int i = tid; i < HH; i += 256) {
        sC[i] = g_c[bb * HH + i];
        sV[i] = vw[i];
    }
    __syncthreads();

    const uint32_t aS0 = smem_u32(smem + A_OFF);
    const uint32_t bS0 = smem_u32(smem + B_OFF);

    // fill-stream: per stage A = 128 rows x 256 B (8 cp16/thr),
    //              B = 64 kp-rows x 1024 B (16 cp16/thr)
    const char* pA0 = (const char*)(encHb + (size_t)(tid >> 4) * HH) + (tid & 15) * 16;
    const char* pB0 = (const char*)g_WeH + (size_t)(tid >> 6) * 4096 + (tid & 63) * 16;
    const char* pA = pA0;
    const char* pB = pB0;
    const uint32_t aDst0 = aS0 + (tid >> 4) * (ASTRH * 2) + (tid & 15) * 16;
    const uint32_t bDst0 = bS0 + (tid >> 6) * (BSTRW * 4) + (tid & 63) * 16;
    int fill_k = 0, fill_nt = 0, fb = 0;

#define DO_FILL() do { \
        const uint32_t ad = aDst0 + fb * ASTG; \
        const uint32_t bd = bDst0 + fb * BSTG; \
        _Pragma("unroll") \
        for (int r = 0; r < 8; r++) \
            cp16(ad + r * 16 * (ASTRH * 2), pA + (size_t)r * 16 * HH * 2); \
        _Pragma("unroll") \
        for (int r = 0; r < 16; r++) \
            cp16(bd + r * 4 * (BSTRW * 4), pB + (size_t)r * 4 * 4096); \
        CP_COMMIT(); \
        fb ^= 1; \
        pA += KSTG * 2; \
        pB += 64 * 4096; \
        if (++fill_k == SPP) { \
            fill_k = 0; fill_nt++; \
            pA = pA0; \
            pB = pB0 + (size_t)fill_nt * 1024; \
        } \
    } while (0)

    float acc[4][8][4];
#pragma unroll
    for (int mi = 0; mi < 4; mi++)
#pragma unroll
        for (int ni = 0; ni < 8; ni++)
#pragma unroll
            for (int e = 0; e < 4; e++) acc[mi][ni][e] = 0.f;
    float rowp[8];
#pragma unroll
    for (int i = 0; i < 8; i++) rowp[i] = 0.f;

    const uint32_t aLd0 = aS0 + (wm * 64 + lm_row) * (ASTRH * 2) + lm_colB;
    const char* bGen0 = smem + B_OFF + (t * BSTRW + wn * 64 + g * 4) * 4;

    DO_FILL();   // stage 0 -> buffer 0

    for (int gs = 0; gs < TOTS; gs++) {
        const int buf = gs & 1;
        asm volatile("cp.async.wait_group 0;" ::: "memory");
        __syncthreads();

        const uint32_t aLd = aLd0 + buf * ASTG;
        const char* bGen = bGen0 + buf * BSTG;

        uint32_t afr[4][4];
        uint32_t b0[8], b1[8];

        // peel: load ks0 fragments BEFORE the fill burst so the first MMA
        // chain is not delayed by 24 cp.async issues
        LOAD_FRAGS(0);
        if (gs + 1 < TOTS) DO_FILL();   // stage gs+1 -> other buffer

#pragma unroll
        for (int ks = 0; ks < 8; ks++) {           // eight k16 steps
#pragma unroll
            for (int mi = 0; mi < 4; mi++)
#pragma unroll
                for (int ni = 0; ni < 8; ni++)
                    asm volatile(
                        "mma.sync.aligned.m16n8k16.row.col.f32.f16.f16.f32 "
                        "{%0,%1,%2,%3}, {%4,%5,%6,%7}, {%8,%9}, {%0,%1,%2,%3};\n"
                        : "+f"(acc[mi][ni][0]), "+f"(acc[mi][ni][1]),
                          "+f"(acc[mi][ni][2]), "+f"(acc[mi][ni][3])
                        : "r"(afr[mi][0]), "r"(afr[mi][1]), "r"(afr[mi][2]),
                          "r"(afr[mi][3]), "r"(b0[ni]), "r"(b1[ni]));
            if (ks < 7) LOAD_FRAGS(ks + 1);   // issue under MMA(ks) drain
        }

        if ((gs & (SPP - 1)) == SPP - 1) {
            const int n0 = (gs / SPP) * NTILE;
#pragma unroll
            for (int mi = 0; mi < 4; mi++)
#pragma unroll
                for (int ni = 0; ni < 8; ni++) {
                    const int tile = wn * 64 + (ni >> 2) * 32 + (ni & 3) * 8;
                    const int hbase = n0 + tile + 2 * t;
#pragma unroll
                    for (int e = 0; e < 4; e++) {
                        const int hh = hbase + (e & 1);
                        rowp[mi * 2 + (e >> 1)] +=
                            sV[hh] * tanh_fast(acc[mi][ni][e] + sC[hh]);
                        acc[mi][ni][e] = 0.f;
                    }
                }
        }
    }

    // reduce the 4 lanes (t) sharing each row
#pragma unroll
    for (int i = 0; i < 8; i++) {
        rowp[i] += __shfl_xor_sync(0xffffffffu, rowp[i], 1);
        rowp[i] += __shfl_xor_sync(0xffffffffu, rowp[i], 2);
    }
    __syncthreads();
    if (t == 0) {
#pragma unroll
        for (int mi = 0; mi < 4; mi++)
#pragma unroll
            for (int p = 0; p < 2; p++) {
                const int r = wm * 64 + mi * 16 + g + p * 8;
                sRed[wn * 128 + r] = rowp[mi * 2 + p];
            }
    }
    __syncthreads();
    if (tid < 128) {
        float a = sRed[tid] + sRed[128 + tid] + sRed[256 + tid] + sRed[384 + tid];
        const int s = m0 + tid;
        if (mask[bb * SS + s] == 1) a = NEGV;
        g_logits[bb * SS + s] = a;
    }
}

// ---------------------------------------------------------------------------
// Softmax over S per batch row
// ---------------------------------------------------------------------------
__global__ void softmax_kernel(float* __restrict__ out) {
    __shared__ float sm[SS];
    __shared__ float red[256];
    const int b = blockIdx.x;
    const int tid = threadIdx.x;
    float mx = -INFINITY;
    for (int i = tid; i < SS; i += 256) {
        float v = g_logits[b * SS + i];
        sm[i] = v;
        mx = fmaxf(mx, v);
    }
    red[tid] = mx;
    __syncthreads();
    for (int o = 128; o > 0; o >>= 1) {
        if (tid < o) red[tid] = fmaxf(red[tid], red[tid + o]);
        __syncthreads();
    }
    mx = red[0];
    __syncthreads();
    float sum = 0.f;
    for (int i = tid; i < SS; i += 256) {
        float e = expf(sm[i] - mx);
        sm[i] = e;
        sum += e;
    }
    red[tid] = sum;
    __syncthreads();
    for (int o = 128; o > 0; o >>= 1) {
        if (tid < o) red[tid] += red[tid + o];
        __syncthreads();
    }
    const float inv = 1.0f / red[0];
    for (int i = tid; i < SS; i += 256) out[b * SS + i] = sm[i] * inv;
}

extern "C" void kernel_launch(void* const* d_in, const int* in_sizes, int n_in,
                              void* d_out, int out_size) {
    const float* dh   = (const float*)d_in[0];
    const float* enc  = (const float*)d_in[1];
    const int*   mask = (const int*)d_in[2];
    const float* Wa   = (const float*)d_in[3];
    const float* ba   = (const float*)d_in[4];
    const float* vw   = (const float*)d_in[5];
    float* out = (float*)d_out;

    cudaFuncSetAttribute(attn_kernel, cudaFuncAttributeMaxDynamicSharedMemorySize, SMEM_TOTAL);

    conv_enc<<<(int)((size_t)BB * SS * HH / (256 * 8)), 256>>>(enc);
    conv_we<<<dim3(HH / 256, HH / 2), 256>>>(Wa);
    decproj_part<<<dim3(8, 8, 4), 128>>>(dh, Wa);
    decproj_reduce<<<BB, 256>>>(ba);
    attn_kernel<<<1024, 256, SMEM_TOTAL>>>(mask, vw);
    softmax_kernel<<<BB, 256>>>(out);
}

// round 17
// speedup vs baseline: 1.4823x; 1.4823x over previous
#include <cuda_runtime.h>
#include <cuda_fp16.h>
#include <math.h>
#include <stdint.h>
#include <stddef.h>

#define BB 64
#define SS 2048
#define HH 1024
#define NEGV -1e10f

// ---------------- tiling (R12 winner: KSTG=128, 2-deep ring) ----------------
#define KSTG 128                    // K elems per pipeline stage (8 x k16)
#define NTILE 256                   // N per pass
#define NPASS 4
#define SPP (HH / KSTG)             // 8 stages per pass
#define TOTS (NPASS * SPP)          // 32 stages
#define ASTRH 136                   // A smem row stride in halves (272 B = 17x16B, LDSM bank-clean)
#define BSTRW 264                   // B smem row stride in words (LDS.128 bank-clean)
#define ASTG (128 * ASTRH * 2)      // 34816 B
#define BSTG (64 * BSTRW * 4)       // 67584 B
#define SC_OFF 0
#define SV_OFF 4096
#define SRED_OFF 8192
#define A_OFF 10240
#define B_OFF (A_OFF + 2 * ASTG)              // 79872
#define SMEM_TOTAL (B_OFF + 2 * BSTG)         // 215040 bytes

__device__ float g_c[BB * HH];
__device__ float g_cpart[8 * BB * HH];
__device__ float g_logits[BB * SS];
__device__ __half g_encH[(size_t)BB * SS * HH];   // enc in fp16
__device__ uint32_t g_WeH[(HH / 2) * HH];         // We fp16x2 (k-pairs), col-permuted

// ---------------- helpers ----------------
static __device__ __forceinline__ float tanh_fast(float x) {
    float y;
    asm("tanh.approx.f32 %0, %1;" : "=f"(y) : "f"(x));
    return y;
}
static __device__ __forceinline__ uint32_t smem_u32(const void* p) {
    uint32_t a;
    asm("{ .reg .u64 t; cvta.to.shared.u64 t, %1; cvt.u32.u64 %0, t; }" : "=r"(a) : "l"(p));
    return a;
}
static __device__ __forceinline__ void cp16(uint32_t d, const void* s) {
    asm volatile("cp.async.cg.shared.global [%0], [%1], 16;" :: "r"(d), "l"(s) : "memory");
}
#define CP_COMMIT() asm volatile("cp.async.commit_group;" ::: "memory")

// ---------------------------------------------------------------------------
// Prep 1a: enc -> fp16
// ---------------------------------------------------------------------------
__global__ void conv_enc(const float* __restrict__ enc) {
    size_t idx = ((size_t)blockIdx.x * 256 + threadIdx.x) * 8;
    const float4 f0 = *(const float4*)(enc + idx);
    const float4 f1 = *(const float4*)(enc + idx + 4);
    __half2 h0 = __floats2half2_rn(f0.x, f0.y);
    __half2 h1 = __floats2half2_rn(f0.z, f0.w);
    __half2 h2 = __floats2half2_rn(f1.x, f1.y);
    __half2 h3 = __floats2half2_rn(f1.z, f1.w);
    uint4 o;
    o.x = *(uint32_t*)&h0; o.y = *(uint32_t*)&h1;
    o.z = *(uint32_t*)&h2; o.w = *(uint32_t*)&h3;
    *(uint4*)(g_encH + idx) = o;
}

// ---------------------------------------------------------------------------
// Prep 1b: We -> fp16x2 k-pair packed, col-permuted within 32-col groups
// ---------------------------------------------------------------------------
__global__ void conv_we(const float* __restrict__ Wa) {
    const float* We = Wa + (size_t)HH * HH;
    const int kp = blockIdx.y;
    const int n = blockIdx.x * 256 + threadIdx.x;
    float a = We[(size_t)(2 * kp) * HH + n];
    float b = We[(size_t)(2 * kp + 1) * HH + n];
    __half2 h = __floats2half2_rn(a, b);
    int r = n & 31;
    int cc = (n & ~31) + (r & 7) * 4 + (r >> 3);
    g_WeH[(size_t)kp * HH + cc] = *(uint32_t*)&h;
}

// ---------------------------------------------------------------------------
// Prep 2: dec_proj k-split partials, batch-split 4x (deterministic)
// ---------------------------------------------------------------------------
__global__ void __launch_bounds__(128) decproj_part(const float* __restrict__ dh,
                                                    const float* __restrict__ Wa) {
    __shared__ float sdh[16 * 128];
    const int tid = threadIdx.x;
    const int h = blockIdx.x * 128 + tid;
    const int k0 = blockIdx.y * 128;
    const int b0 = blockIdx.z * 16;
    for (int i = tid; i < 16 * 128; i += 128) {
        int b = i >> 7, kk = i & 127;
        sdh[i] = dh[(b0 + b) * HH + k0 + kk];
    }
    __syncthreads();
    float acc[16];
#pragma unroll
    for (int b = 0; b < 16; b++) acc[b] = 0.f;
    for (int kk = 0; kk < 128; kk++) {
        float w = Wa[(size_t)(k0 + kk) * HH + h];
#pragma unroll
        for (int b = 0; b < 16; b++) acc[b] += sdh[b * 128 + kk] * w;
    }
#pragma unroll
    for (int b = 0; b < 16; b++)
        g_cpart[((size_t)blockIdx.y * BB + b0 + b) * HH + h] = acc[b];
}

// grid 256: block = (b, quarter of h-range); identical summation order
__global__ void decproj_reduce(const float* __restrict__ ba) {
    const int b = blockIdx.x >> 2;
    const int h = (blockIdx.x & 3) * 256 + threadIdx.x;
    float s = ba[h];
#pragma unroll
    for (int kc = 0; kc < 8; kc++) s += g_cpart[((size_t)kc * BB + b) * HH + h];
    g_c[b * HH + h] = s;
}

// ---------------------------------------------------------------------------
// Fused main: fp16 m16n8k16, 256 threads (2wm x 4wn, M64 x N64 warp tile),
// KSTG=128 (8 x k16), 2-deep cp.async ring -> 32 stages / 32 barriers total.
// ---------------------------------------------------------------------------
__global__ void __launch_bounds__(256, 1) attn_kernel(const int* __restrict__ mask,
                                                      const float* __restrict__ vw) {
    extern __shared__ char smem[];
    float* sC = (float*)(smem + SC_OFF);
    float* sV = (float*)(smem + SV_OFF);
    float* sRed = (float*)(smem + SRED_OFF);

    const int tid = threadIdx.x;
    const int wid = tid >> 5, lane = tid & 31;
    const int wm = wid & 1;        // 2 warps along M (64 rows each)
    const int wn = wid >> 1;       // 4 warps along N (64 cols each)
    const int g = lane >> 2, t = lane & 3;
    const int cta = blockIdx.x;
    const int bb = cta >> 4;
    const int m0 = (cta & 15) * 128;
    const __half* encHb = g_encH + ((size_t)bb * SS + m0) * HH;

    // ldmatrix b16 x4 lane offsets
    const int ltile = lane >> 3, lrow = lane & 7;
    const int lm_row = (ltile & 1) * 8 + lrow;
    const int lm_colB = (ltile >> 1) * 16;

    for (int i = tid; i < HH; i += 256) {
        sC[i] = g_c[bb * HH + i];
        sV[i] = vw[i];
    }
    __syncthreads();

    const uint32_t aS0 = smem_u32(smem + A_OFF);
    const uint32_t bS0 = smem_u32(smem + B_OFF);

    // fill-stream: per stage A = 128 rows x 256 B (8 cp16/thr),
    //              B = 64 kp-rows x 1024 B (16 cp16/thr)
    const char* pA0 = (const char*)(encHb + (size_t)(tid >> 4) * HH) + (tid & 15) * 16;
    const char* pB0 = (const char*)g_WeH + (size_t)(tid >> 6) * 4096 + (tid & 63) * 16;
    const char* pA = pA0;
    const char* pB = pB0;
    const uint32_t aDst0 = aS0 + (tid >> 4) * (ASTRH * 2) + (tid & 15) * 16;
    const uint32_t bDst0 = bS0 + (tid >> 6) * (BSTRW * 4) + (tid & 63) * 16;
    int fill_k = 0, fill_nt = 0, fb = 0;

#define DO_FILL() do { \
        const uint32_t ad = aDst0 + fb * ASTG; \
        const uint32_t bd = bDst0 + fb * BSTG; \
        _Pragma("unroll") \
        for (int r = 0; r < 8; r++) \
            cp16(ad + r * 16 * (ASTRH * 2), pA + (size_t)r * 16 * HH * 2); \
        _Pragma("unroll") \
        for (int r = 0; r < 16; r++) \
            cp16(bd + r * 4 * (BSTRW * 4), pB + (size_t)r * 4 * 4096); \
        CP_COMMIT(); \
        fb ^= 1; \
        pA += KSTG * 2; \
        pB += 64 * 4096; \
        if (++fill_k == SPP) { \
            fill_k = 0; fill_nt++; \
            pA = pA0; \
            pB = pB0 + (size_t)fill_nt * 1024; \
        } \
    } while (0)

    float acc[4][8][4];
#pragma unroll
    for (int mi = 0; mi < 4; mi++)
#pragma unroll
        for (int ni = 0; ni < 8; ni++)
#pragma unroll
            for (int e = 0; e < 4; e++) acc[mi][ni][e] = 0.f;
    float rowp[8];
#pragma unroll
    for (int i = 0; i < 8; i++) rowp[i] = 0.f;

    const uint32_t aLd0 = aS0 + (wm * 64 + lm_row) * (ASTRH * 2) + lm_colB;
    const char* bGen0 = smem + B_OFF + (t * BSTRW + wn * 64 + g * 4) * 4;

    DO_FILL();   // stage 0 -> buffer 0

    for (int gs = 0; gs < TOTS; gs++) {
        const int buf = gs & 1;
        asm volatile("cp.async.wait_group 0;" ::: "memory");
        __syncthreads();
        if (gs + 1 < TOTS) DO_FILL();   // stage gs+1 -> other buffer

        const uint32_t aLd = aLd0 + buf * ASTG;
        const char* bGen = bGen0 + buf * BSTG;

#pragma unroll
        for (int ks = 0; ks < 8; ks++) {           // eight k16 steps
            uint32_t afr[4][4];
#pragma unroll
            for (int mi = 0; mi < 4; mi++)
                asm volatile(
                    "ldmatrix.sync.aligned.m8n8.x4.shared.b16 {%0,%1,%2,%3}, [%4];"
                    : "=r"(afr[mi][0]), "=r"(afr[mi][1]),
                      "=r"(afr[mi][2]), "=r"(afr[mi][3])
                    : "r"(aLd + mi * 16 * (ASTRH * 2) + ks * 32));
            const char* bk = bGen + ks * 8 * (BSTRW * 4);
            const uint4 x0g0 = *(const uint4*)(bk);
            const uint4 x0g1 = *(const uint4*)(bk + 128);
            const uint4 x1g0 = *(const uint4*)(bk + 4 * (BSTRW * 4));
            const uint4 x1g1 = *(const uint4*)(bk + 4 * (BSTRW * 4) + 128);
            const uint32_t b0[8] = {x0g0.x, x0g0.y, x0g0.z, x0g0.w,
                                    x0g1.x, x0g1.y, x0g1.z, x0g1.w};
            const uint32_t b1[8] = {x1g0.x, x1g0.y, x1g0.z, x1g0.w,
                                    x1g1.x, x1g1.y, x1g1.z, x1g1.w};
#pragma unroll
            for (int mi = 0; mi < 4; mi++)
#pragma unroll
                for (int ni = 0; ni < 8; ni++)
                    asm volatile(
                        "mma.sync.aligned.m16n8k16.row.col.f32.f16.f16.f32 "
                        "{%0,%1,%2,%3}, {%4,%5,%6,%7}, {%8,%9}, {%0,%1,%2,%3};\n"
                        : "+f"(acc[mi][ni][0]), "+f"(acc[mi][ni][1]),
                          "+f"(acc[mi][ni][2]), "+f"(acc[mi][ni][3])
                        : "r"(afr[mi][0]), "r"(afr[mi][1]), "r"(afr[mi][2]),
                          "r"(afr[mi][3]), "r"(b0[ni]), "r"(b1[ni]));
        }

        if ((gs & (SPP - 1)) == SPP - 1) {
            const int n0 = (gs / SPP) * NTILE;
#pragma unroll
            for (int mi = 0; mi < 4; mi++)
#pragma unroll
                for (int ni = 0; ni < 8; ni++) {
                    const int tile = wn * 64 + (ni >> 2) * 32 + (ni & 3) * 8;
                    const int hbase = n0 + tile + 2 * t;
#pragma unroll
                    for (int e = 0; e < 4; e++) {
                        const int hh = hbase + (e & 1);
                        rowp[mi * 2 + (e >> 1)] +=
                            sV[hh] * tanh_fast(acc[mi][ni][e] + sC[hh]);
                        acc[mi][ni][e] = 0.f;
                    }
                }
        }
    }

    // reduce the 4 lanes (t) sharing each row
#pragma unroll
    for (int i = 0; i < 8; i++) {
        rowp[i] += __shfl_xor_sync(0xffffffffu, rowp[i], 1);
        rowp[i] += __shfl_xor_sync(0xffffffffu, rowp[i], 2);
    }
    __syncthreads();
    if (t == 0) {
#pragma unroll
        for (int mi = 0; mi < 4; mi++)
#pragma unroll
            for (int p = 0; p < 2; p++) {
                const int r = wm * 64 + mi * 16 + g + p * 8;
                sRed[wn * 128 + r] = rowp[mi * 2 + p];
            }
    }
    __syncthreads();
    if (tid < 128) {
        float a = sRed[tid] + sRed[128 + tid] + sRed[256 + tid] + sRed[384 + tid];
        const int s = m0 + tid;
        if (mask[bb * SS + s] == 1) a = NEGV;
        g_logits[bb * SS + s] = a;
    }
}

// ---------------------------------------------------------------------------
// Softmax over S per batch row
// ---------------------------------------------------------------------------
__global__ void softmax_kernel(float* __restrict__ out) {
    __shared__ float sm[SS];
    __shared__ float red[256];
    const int b = blockIdx.x;
    const int tid = threadIdx.x;
    float mx = -INFINITY;
    for (int i = tid; i < SS; i += 256) {
        float v = g_logits[b * SS + i];
        sm[i] = v;
        mx = fmaxf(mx, v);
    }
    red[tid] = mx;
    __syncthreads();
    for (int o = 128; o > 0; o >>= 1) {
        if (tid < o) red[tid] = fmaxf(red[tid], red[tid + o]);
        __syncthreads();
    }
    mx = red[0];
    __syncthreads();
    float sum = 0.f;
    for (int i = tid; i < SS; i += 256) {
        float e = expf(sm[i] - mx);
        sm[i] = e;
        sum += e;
    }
    red[tid] = sum;
    __syncthreads();
    for (int o = 128; o > 0; o >>= 1) {
        if (tid < o) red[tid] += red[tid + o];
        __syncthreads();
    }
    const float inv = 1.0f / red[0];
    for (int i = tid; i < SS; i += 256) out[b * SS + i] = sm[i] * inv;
}

extern "C" void kernel_launch(void* const* d_in, const int* in_sizes, int n_in,
                              void* d_out, int out_size) {
    const float* dh   = (const float*)d_in[0];
    const float* enc  = (const float*)d_in[1];
    const int*   mask = (const int*)d_in[2];
    const float* Wa   = (const float*)d_in[3];
    const float* ba   = (const float*)d_in[4];
    const float* vw   = (const float*)d_in[5];
    float* out = (float*)d_out;

    cudaFuncSetAttribute(attn_kernel, cudaFuncAttributeMaxDynamicSharedMemorySize, SMEM_TOTAL);

    conv_enc<<<(int)((size_t)BB * SS * HH / (256 * 8)), 256>>>(enc);
    conv_we<<<dim3(HH / 256, HH / 2), 256>>>(Wa);
    decproj_part<<<dim3(8, 8, 4), 128>>>(dh, Wa);
    decproj_reduce<<<4 * BB, 256>>>(ba);
    attn_kernel<<<1024, 256, SMEM_TOTAL>>>(mask, vw);
    softmax_kernel<<<BB, 256>>>(out);
}